// round 1
// baseline (speedup 1.0000x reference)
#include <cuda_runtime.h>
#include <math.h>

// ---------------- problem constants ----------------
#define NB   128
#define SSEG 20
#define DDICT 1000
#define LSEG 200
#define OUTDIM 62      // 2 + 3*20

// ---------------- scratch (device globals: no allocation allowed) ----------------
__device__ float g_h1[(size_t)NB*64*49*49];     // after stage1
__device__ float g_h2[(size_t)NB*128*23*23];    // after stage2
__device__ float g_h3[(size_t)NB*256*10*10];    // after stage3
__device__ float g_h4[(size_t)NB*512*4*4];      // after stage4 (= flatten 8192)
__device__ float g_a1[NB*2048];
__device__ float g_a2[NB*2048];
__device__ float g_p [NB*OUTDIM];
__device__ float g_w1p[64*3*12];
__device__ float g_w2p[128*64*12];
__device__ float g_w3p[256*128*12];
__device__ float g_w4p[512*256*12];

// ---------------- weight repack: 9 floats -> 12 floats (16B aligned) ----------------
__global__ void repack_w_kernel(const float* __restrict__ w, float* __restrict__ wp, int ngroups)
{
    int i = blockIdx.x * blockDim.x + threadIdx.x;
    if (i >= ngroups * 12) return;
    int g = i / 12, j = i % 12;
    wp[i] = (j < 9) ? w[g * 9 + j] : 0.0f;
}

// ---------------- fused conv3x3(VALID) + bias + maxpool2 + relu ----------------
// Each thread: one pooled output position for 8 consecutive output channels.
template<int CIN, int HIN, int WIN, int HP, int WP, int COUT>
__global__ void conv_pool_relu(const float* __restrict__ in,
                               const float* __restrict__ wp,    // packed [COUT][CIN][12]
                               const float* __restrict__ bias,
                               float* __restrict__ out)
{
    constexpr int COG = COUT / 8;
    int idx = blockIdx.x * blockDim.x + threadIdx.x;
    const int total = NB * COG * HP * WP;
    if (idx >= total) return;

    int pw = idx % WP;  int t = idx / WP;
    int ph = t % HP;    t /= HP;
    int cg = t % COG;   t /= COG;
    int b  = t;
    int co0 = cg * 8;

    float acc[8][4];
    #pragma unroll
    for (int i = 0; i < 8; i++)
        #pragma unroll
        for (int j = 0; j < 4; j++) acc[i][j] = 0.0f;

    const float* inb = in + ((size_t)b * CIN * HIN + 2 * ph) * WIN + 2 * pw;

    for (int ci = 0; ci < CIN; ci++) {
        const float* ip = inb + (size_t)ci * HIN * WIN;
        float xv[16];
        #pragma unroll
        for (int r = 0; r < 4; r++)
            #pragma unroll
            for (int c = 0; c < 4; c++)
                xv[r * 4 + c] = __ldg(ip + r * WIN + c);

        #pragma unroll
        for (int co = 0; co < 8; co++) {
            const float4* w4 = reinterpret_cast<const float4*>(wp + ((size_t)(co0 + co) * CIN + ci) * 12);
            float4 wa = __ldg(w4), wb = __ldg(w4 + 1), wc = __ldg(w4 + 2);
            float wv[9] = {wa.x, wa.y, wa.z, wa.w, wb.x, wb.y, wb.z, wb.w, wc.x};
            #pragma unroll
            for (int dy = 0; dy < 2; dy++)
                #pragma unroll
                for (int dx = 0; dx < 2; dx++) {
                    float s = acc[co][dy * 2 + dx];
                    #pragma unroll
                    for (int kh = 0; kh < 3; kh++)
                        #pragma unroll
                        for (int kw = 0; kw < 3; kw++)
                            s = fmaf(xv[(dy + kh) * 4 + dx + kw], wv[kh * 3 + kw], s);
                    acc[co][dy * 2 + dx] = s;
                }
        }
    }

    #pragma unroll
    for (int co = 0; co < 8; co++) {
        float m = fmaxf(fmaxf(acc[co][0], acc[co][1]), fmaxf(acc[co][2], acc[co][3]))
                  + __ldg(bias + co0 + co);
        out[(((size_t)b * COUT + co0 + co) * HP + ph) * WP + pw] = fmaxf(m, 0.0f);
    }
}

// ---------------- tiled SGEMM: C = act(A[MxK] @ B[KxN] + bias), row-major ----------------
// BM=BN=64, BK=16, 256 threads, 4x4 per thread. Requires M%64==0, N%64==0, K%16==0.
template<int ACT>  // 0 = none, 1 = tanh
__global__ void gemm64(const float* __restrict__ A, const float* __restrict__ B,
                       const float* __restrict__ bias, float* __restrict__ C,
                       int M, int N, int K)
{
    const int BM = 64, BN = 64, BK = 16;
    __shared__ float As[BK][BM];
    __shared__ float Bs[BK][BN + 1];
    int tx = threadIdx.x % 16, ty = threadIdx.x / 16;
    int m0 = blockIdx.y * BM, n0 = blockIdx.x * BN;

    float acc[4][4] = {};
    for (int kk = 0; kk < K; kk += BK) {
        #pragma unroll
        for (int i = 0; i < 4; i++) {
            int l = threadIdx.x + i * 256;
            int m = l / 16, k = l % 16;
            As[k][m] = A[(size_t)(m0 + m) * K + kk + k];
        }
        #pragma unroll
        for (int i = 0; i < 4; i++) {
            int l = threadIdx.x + i * 256;
            int n = l % 64, k = l / 64;
            Bs[k][n] = B[(size_t)(kk + k) * N + n0 + n];
        }
        __syncthreads();
        #pragma unroll
        for (int k = 0; k < BK; k++) {
            float a[4], bf[4];
            #pragma unroll
            for (int i = 0; i < 4; i++) a[i] = As[k][ty * 4 + i];
            #pragma unroll
            for (int j = 0; j < 4; j++) bf[j] = Bs[k][tx * 4 + j];
            #pragma unroll
            for (int i = 0; i < 4; i++)
                #pragma unroll
                for (int j = 0; j < 4; j++)
                    acc[i][j] = fmaf(a[i], bf[j], acc[i][j]);
        }
        __syncthreads();
    }

    #pragma unroll
    for (int i = 0; i < 4; i++) {
        int m = m0 + ty * 4 + i;
        #pragma unroll
        for (int j = 0; j < 4; j++) {
            int n = n0 + tx * 4 + j;
            float v = acc[i][j] + __ldg(bias + n);
            if (ACT == 1) v = tanhf(v);
            C[(size_t)m * N + n] = v;
        }
    }
}

// ---------------- small FC (fc3: 2048 -> 62), one block per row ----------------
__global__ void fc_small(const float* __restrict__ A, const float* __restrict__ W,
                         const float* __restrict__ bias, float* __restrict__ C,
                         int N, int K)
{
    int n = threadIdx.x;
    int m = blockIdx.x;
    if (n >= N) return;
    float acc = __ldg(bias + n);
    const float* a = A + (size_t)m * K;
    for (int k = 0; k < K; k++)
        acc = fmaf(__ldg(a + k), __ldg(W + (size_t)k * N + n), acc);
    C[(size_t)m * N + n] = acc;
}

// ---------------- trajectory assembly ----------------
// p: [B, 62], dict: [1000, 200, 2], out: [B, 4000, 2]
__global__ void traj_kernel(const float* __restrict__ p, const float* __restrict__ dict,
                            float* __restrict__ out)
{
    int b = blockIdx.x;
    __shared__ float sx[SSEG], sy[SSEG], s1[SSEG], s2[SSEG];
    __shared__ int sidx[SSEG];

    if (threadIdx.x == 0) {
        float cx = p[b * OUTDIM + 0];
        float cy = p[b * OUTDIM + 1];
        for (int s = 0; s < SSEG; s++) {
            float f0  = p[b * OUTDIM + 2 + s * 3 + 0];
            float sc1 = p[b * OUTDIM + 2 + s * 3 + 1];
            float sc2 = p[b * OUTDIM + 2 + s * 3 + 2];
            float r = rintf(f0);                       // ties-to-even, matches jnp.round
            r = fminf(fmaxf(r, 0.0f), (float)(DDICT - 1));
            int id = (int)r;
            sidx[s] = id; s1[s] = sc1; s2[s] = sc2;
            sx[s] = cx; sy[s] = cy;                    // exclusive cumsum of offsets
            cx += dict[((size_t)id * LSEG + (LSEG - 1)) * 2 + 0] * sc1;
            cy += dict[((size_t)id * LSEG + (LSEG - 1)) * 2 + 1] * sc2;
        }
    }
    __syncthreads();

    for (int i = threadIdx.x; i < SSEG * LSEG; i += blockDim.x) {
        int s = i / LSEG, l = i % LSEG;
        int id = sidx[s];
        float bx = dict[((size_t)id * LSEG + l) * 2 + 0];
        float by = dict[((size_t)id * LSEG + l) * 2 + 1];
        out[((size_t)b * SSEG * LSEG + i) * 2 + 0] = fmaf(bx, s1[s], sx[s]);
        out[((size_t)b * SSEG * LSEG + i) * 2 + 1] = fmaf(by, s2[s], sy[s]);
    }
}

// ---------------- launch ----------------
extern "C" void kernel_launch(void* const* d_in, const int* in_sizes, int n_in,
                              void* d_out, int out_size)
{
    const float* x   = (const float*)d_in[0];
    const float* w1  = (const float*)d_in[1];
    const float* b1  = (const float*)d_in[2];
    const float* w2  = (const float*)d_in[3];
    const float* b2  = (const float*)d_in[4];
    const float* w3  = (const float*)d_in[5];
    const float* b3  = (const float*)d_in[6];
    const float* w4  = (const float*)d_in[7];
    const float* b4  = (const float*)d_in[8];
    const float* fw1 = (const float*)d_in[9];
    const float* fb1 = (const float*)d_in[10];
    const float* fw2 = (const float*)d_in[11];
    const float* fb2 = (const float*)d_in[12];
    const float* fw3 = (const float*)d_in[13];
    const float* fb3 = (const float*)d_in[14];
    const float* dict= (const float*)d_in[15];
    float* out = (float*)d_out;

    float *h1, *h2, *h3, *h4, *a1, *a2, *pp, *w1p, *w2p, *w3p, *w4p;
    cudaGetSymbolAddress((void**)&h1,  g_h1);
    cudaGetSymbolAddress((void**)&h2,  g_h2);
    cudaGetSymbolAddress((void**)&h3,  g_h3);
    cudaGetSymbolAddress((void**)&h4,  g_h4);
    cudaGetSymbolAddress((void**)&a1,  g_a1);
    cudaGetSymbolAddress((void**)&a2,  g_a2);
    cudaGetSymbolAddress((void**)&pp,  g_p);
    cudaGetSymbolAddress((void**)&w1p, g_w1p);
    cudaGetSymbolAddress((void**)&w2p, g_w2p);
    cudaGetSymbolAddress((void**)&w3p, g_w3p);
    cudaGetSymbolAddress((void**)&w4p, g_w4p);

    // weight repack (cheap; part of the deterministic graph)
    repack_w_kernel<<<(64*3*12   + 255) / 256, 256>>>(w1, w1p, 64*3);
    repack_w_kernel<<<(128*64*12 + 255) / 256, 256>>>(w2, w2p, 128*64);
    repack_w_kernel<<<(256*128*12+ 255) / 256, 256>>>(w3, w3p, 256*128);
    repack_w_kernel<<<(512*256*12+ 255) / 256, 256>>>(w4, w4p, 512*256);

    // stage 1: (128,3,100,100) -> (128,64,49,49)
    {
        int total = NB * (64/8) * 49 * 49;
        conv_pool_relu<3,100,100,49,49,64><<<(total + 255) / 256, 256>>>(x, w1p, b1, h1);
    }
    // stage 2: -> (128,128,23,23)
    {
        int total = NB * (128/8) * 23 * 23;
        conv_pool_relu<64,49,49,23,23,128><<<(total + 255) / 256, 256>>>(h1, w2p, b2, h2);
    }
    // stage 3: -> (128,256,10,10)
    {
        int total = NB * (256/8) * 10 * 10;
        conv_pool_relu<128,23,23,10,10,256><<<(total + 255) / 256, 256>>>(h2, w3p, b3, h3);
    }
    // stage 4: -> (128,512,4,4)  == flatten (128, 8192)
    {
        int total = NB * (512/8) * 4 * 4;
        conv_pool_relu<256,10,10,4,4,512><<<(total + 255) / 256, 256>>>(h3, w4p, b4, h4);
    }

    // fc1: (128,8192) @ (8192,2048) + tanh
    {
        dim3 grid(2048 / 64, NB / 64);
        gemm64<1><<<grid, 256>>>(h4, fw1, fb1, a1, NB, 2048, 8192);
    }
    // fc2: (128,2048) @ (2048,2048) + tanh
    {
        dim3 grid(2048 / 64, NB / 64);
        gemm64<1><<<grid, 256>>>(a1, fw2, fb2, a2, NB, 2048, 2048);
    }
    // fc3: (128,2048) @ (2048,62)
    fc_small<<<NB, 64>>>(a2, fw3, fb3, pp, OUTDIM, 2048);

    // trajectory assembly -> (128, 4000, 2)
    traj_kernel<<<NB, 256>>>(pp, dict, out);
}

// round 3
// speedup vs baseline: 1.1618x; 1.1618x over previous
#include <cuda_runtime.h>
#include <math.h>

typedef unsigned long long u64;

// ---------------- problem constants ----------------
#define NB   128
#define SSEG 20
#define DDICT 1000
#define LSEG 200
#define OUTDIM 62      // 2 + 3*20

// ---------------- f32x2 helpers (FFMA2: 2 IEEE fp32 FMAs / instruction) ----------------
__device__ __forceinline__ u64 pack2(float a, float b) {
    u64 r; asm("mov.b64 %0, {%1, %2};" : "=l"(r) : "f"(a), "f"(b)); return r;
}
__device__ __forceinline__ u64 fma2(u64 a, u64 b, u64 c) {
    u64 d; asm("fma.rn.f32x2 %0, %1, %2, %3;" : "=l"(d) : "l"(a), "l"(b), "l"(c)); return d;
}
__device__ __forceinline__ void unpack2(u64 v, float& lo, float& hi) {
    asm("mov.b64 {%0, %1}, %2;" : "=f"(lo), "=f"(hi) : "l"(v));
}

// ---------------- scratch (device globals: no allocation allowed) ----------------
__device__ float g_h1[(size_t)NB*64*49*49];
__device__ float g_h2[(size_t)NB*128*23*23];
__device__ float g_h3[(size_t)NB*256*10*10];
__device__ float g_h4[(size_t)NB*512*4*4];
__device__ float g_a1[NB*2048];
__device__ float g_a2[NB*2048];
__device__ float g_part[2*NB*2048];
__device__ float g_p [NB*OUTDIM];
__device__ float g_w1k[64*3*9];
__device__ float g_w2k[128*64*9];
__device__ float g_w3k[256*128*9];
__device__ float g_w4k[512*256*9];

// ---------------- weight repack: [COUT][CIN][3][3] -> [cg8][ci][k9][c8] ----------------
__global__ void repack_wk(const float* __restrict__ w, float* __restrict__ wk, int CIN, int COUT)
{
    int i = blockIdx.x * blockDim.x + threadIdx.x;
    int total = COUT * CIN * 9;
    if (i >= total) return;
    int c  = i % 8;
    int k  = (i / 8) % 9;
    int ci = (i / 72) % CIN;
    int cg = i / (72 * CIN);
    wk[i] = w[((size_t)(cg * 8 + c) * CIN + ci) * 9 + k];
}

// ---------------- fused conv3x3(VALID) + bias + maxpool2 + relu, FFMA2 over channel pairs ----
// Each thread: one pooled output position for 8 consecutive output channels (4 f32x2 pairs).
template<int CIN, int HIN, int WIN, int HP, int WP, int COUT>
__global__ __launch_bounds__(256)
void conv_pool_relu2(const float* __restrict__ in,
                     const float* __restrict__ wk,   // [cg8][ci][k9][c8]
                     const float* __restrict__ bias,
                     float* __restrict__ out)
{
    constexpr int COG = COUT / 8;
    int idx = blockIdx.x * blockDim.x + threadIdx.x;
    const int total = NB * COG * HP * WP;
    if (idx >= total) return;

    int pw = idx % WP;  int t = idx / WP;
    int ph = t % HP;    t /= HP;
    int cg = t % COG;   t /= COG;
    int b  = t;
    int co0 = cg * 8;

    u64 acc2[4][4];   // [channel pair][pooled quad pos dy*2+dx]
    #pragma unroll
    for (int p = 0; p < 4; p++)
        #pragma unroll
        for (int j = 0; j < 4; j++) acc2[p][j] = 0ull;

    const float* inb = in + ((size_t)b * CIN * HIN + 2 * ph) * WIN + 2 * pw;
    const ulonglong2* __restrict__ wbase =
        reinterpret_cast<const ulonglong2*>(wk + (size_t)cg * CIN * 72);

    for (int ci = 0; ci < CIN; ci++) {
        const float* ip = inb + (size_t)ci * HIN * WIN;
        u64 xx[16];
        #pragma unroll
        for (int r = 0; r < 4; r++)
            #pragma unroll
            for (int c = 0; c < 4; c++) {
                float v = __ldg(ip + r * WIN + c);
                xx[r * 4 + c] = pack2(v, v);
            }

        const ulonglong2* wp = wbase + (size_t)ci * 18;   // 9 k * 2 ulonglong2
        #pragma unroll
        for (int k = 0; k < 9; k++) {
            ulonglong2 wA = wp[2 * k];       // pairs {c0,c1},{c2,c3}
            ulonglong2 wB = wp[2 * k + 1];   // pairs {c4,c5},{c6,c7}
            u64 wpair[4] = {wA.x, wA.y, wB.x, wB.y};
            int kh = k / 3, kw = k % 3;
            #pragma unroll
            for (int p = 0; p < 4; p++)
                #pragma unroll
                for (int dy = 0; dy < 2; dy++)
                    #pragma unroll
                    for (int dx = 0; dx < 2; dx++)
                        acc2[p][dy * 2 + dx] =
                            fma2(xx[(dy + kh) * 4 + dx + kw], wpair[p], acc2[p][dy * 2 + dx]);
        }
    }

    #pragma unroll
    for (int p = 0; p < 4; p++) {
        float l0, h0, l1, h1, l2, h2, l3, h3;
        unpack2(acc2[p][0], l0, h0);
        unpack2(acc2[p][1], l1, h1);
        unpack2(acc2[p][2], l2, h2);
        unpack2(acc2[p][3], l3, h3);
        float mlo = fmaxf(fmaxf(l0, l1), fmaxf(l2, l3)) + __ldg(bias + co0 + 2 * p);
        float mhi = fmaxf(fmaxf(h0, h1), fmaxf(h2, h3)) + __ldg(bias + co0 + 2 * p + 1);
        size_t o0 = (((size_t)b * COUT + co0 + 2 * p) * HP + ph) * WP + pw;
        out[o0]           = fmaxf(mlo, 0.0f);
        out[o0 + (size_t)HP * WP] = fmaxf(mhi, 0.0f);
    }
}

// ---------------- tiled SGEMM (FFMA2): C = act(A[MxK] @ B[KxN] + bias) ----------------
// BM=BN=64, BK=16, 256 threads, 4x4 per thread (4 m x 2 f32x2 n-pairs).
template<int ACT>  // 0 = none, 1 = tanh
__global__ __launch_bounds__(256)
void gemm64v2(const float* __restrict__ A, const float* __restrict__ B,
              const float* __restrict__ bias, float* __restrict__ C,
              int M, int N, int K)
{
    const int BM = 64, BN = 64, BK = 16;
    __shared__ float As[BK][BM + 1];
    __shared__ float Bs[BK][BN];
    int tx = threadIdx.x % 16, ty = threadIdx.x / 16;
    int m0 = blockIdx.y * BM, n0 = blockIdx.x * BN;

    u64 acc[4][2] = {};
    for (int kk = 0; kk < K; kk += BK) {
        #pragma unroll
        for (int i = 0; i < 4; i++) {
            int l = threadIdx.x + i * 256;
            int m = l / 16, k = l % 16;
            As[k][m] = A[(size_t)(m0 + m) * K + kk + k];
        }
        #pragma unroll
        for (int i = 0; i < 4; i++) {
            int l = threadIdx.x + i * 256;
            int n = l % 64, k = l / 64;
            Bs[k][n] = B[(size_t)(kk + k) * N + n0 + n];
        }
        __syncthreads();
        #pragma unroll
        for (int k = 0; k < BK; k++) {
            u64 b0 = *reinterpret_cast<const u64*>(&Bs[k][tx * 4]);
            u64 b1 = *reinterpret_cast<const u64*>(&Bs[k][tx * 4 + 2]);
            #pragma unroll
            for (int i = 0; i < 4; i++) {
                float a = As[k][ty * 4 + i];
                u64 ap = pack2(a, a);
                acc[i][0] = fma2(ap, b0, acc[i][0]);
                acc[i][1] = fma2(ap, b1, acc[i][1]);
            }
        }
        __syncthreads();
    }

    #pragma unroll
    for (int i = 0; i < 4; i++) {
        int m = m0 + ty * 4 + i;
        #pragma unroll
        for (int j = 0; j < 2; j++) {
            float lo, hi;
            unpack2(acc[i][j], lo, hi);
            int n = n0 + tx * 4 + j * 2;
            float v0 = lo + __ldg(bias + n);
            float v1 = hi + __ldg(bias + n + 1);
            if (ACT == 1) { v0 = tanhf(v0); v1 = tanhf(v1); }
            C[(size_t)m * N + n]     = v0;
            C[(size_t)m * N + n + 1] = v1;
        }
    }
}

// ---------------- split-K partial GEMM (no bias/act), z = K-slice ----------------
__global__ __launch_bounds__(256)
void gemm64_part(const float* __restrict__ A, const float* __restrict__ B,
                 float* __restrict__ Cpart, int M, int N, int K, int Ks)
{
    const int BM = 64, BN = 64, BK = 16;
    __shared__ float As[BK][BM + 1];
    __shared__ float Bs[BK][BN];
    int tx = threadIdx.x % 16, ty = threadIdx.x / 16;
    int m0 = blockIdx.y * BM, n0 = blockIdx.x * BN;
    int z = blockIdx.z;
    int k0 = z * Ks;
    float* Cz = Cpart + (size_t)z * M * N;

    u64 acc[4][2] = {};
    for (int kk = k0; kk < k0 + Ks; kk += BK) {
        #pragma unroll
        for (int i = 0; i < 4; i++) {
            int l = threadIdx.x + i * 256;
            int m = l / 16, k = l % 16;
            As[k][m] = A[(size_t)(m0 + m) * K + kk + k];
        }
        #pragma unroll
        for (int i = 0; i < 4; i++) {
            int l = threadIdx.x + i * 256;
            int n = l % 64, k = l / 64;
            Bs[k][n] = B[(size_t)(kk + k) * N + n0 + n];
        }
        __syncthreads();
        #pragma unroll
        for (int k = 0; k < BK; k++) {
            u64 b0 = *reinterpret_cast<const u64*>(&Bs[k][tx * 4]);
            u64 b1 = *reinterpret_cast<const u64*>(&Bs[k][tx * 4 + 2]);
            #pragma unroll
            for (int i = 0; i < 4; i++) {
                float a = As[k][ty * 4 + i];
                u64 ap = pack2(a, a);
                acc[i][0] = fma2(ap, b0, acc[i][0]);
                acc[i][1] = fma2(ap, b1, acc[i][1]);
            }
        }
        __syncthreads();
    }

    #pragma unroll
    for (int i = 0; i < 4; i++) {
        int m = m0 + ty * 4 + i;
        #pragma unroll
        for (int j = 0; j < 2; j++) {
            float lo, hi;
            unpack2(acc[i][j], lo, hi);
            int n = n0 + tx * 4 + j * 2;
            Cz[(size_t)m * N + n]     = lo;
            Cz[(size_t)m * N + n + 1] = hi;
        }
    }
}

__global__ void combine_tanh(const float* __restrict__ part, const float* __restrict__ bias,
                             float* __restrict__ C, int M, int N)
{
    int i = blockIdx.x * blockDim.x + threadIdx.x;
    if (i >= M * N) return;
    int n = i % N;
    C[i] = tanhf(part[i] + part[(size_t)M * N + i] + __ldg(bias + n));
}

// ---------------- small FC (fc3: 2048 -> 62) ----------------
__global__ void fc_small(const float* __restrict__ A, const float* __restrict__ W,
                         const float* __restrict__ bias, float* __restrict__ C,
                         int N, int K)
{
    int n = threadIdx.x;
    int m = blockIdx.x;
    if (n >= N) return;
    float acc = __ldg(bias + n);
    const float* a = A + (size_t)m * K;
    #pragma unroll 4
    for (int k = 0; k < K; k++)
        acc = fmaf(__ldg(a + k), __ldg(W + (size_t)k * N + n), acc);
    C[(size_t)m * N + n] = acc;
}

// ---------------- trajectory assembly ----------------
__global__ void traj_kernel(const float* __restrict__ p, const float* __restrict__ dict,
                            float* __restrict__ out)
{
    int b = blockIdx.x;
    __shared__ float sx[SSEG], sy[SSEG], s1[SSEG], s2[SSEG];
    __shared__ int sidx[SSEG];

    if (threadIdx.x == 0) {
        float cx = p[b * OUTDIM + 0];
        float cy = p[b * OUTDIM + 1];
        for (int s = 0; s < SSEG; s++) {
            float f0  = p[b * OUTDIM + 2 + s * 3 + 0];
            float sc1 = p[b * OUTDIM + 2 + s * 3 + 1];
            float sc2 = p[b * OUTDIM + 2 + s * 3 + 2];
            float r = rintf(f0);
            r = fminf(fmaxf(r, 0.0f), (float)(DDICT - 1));
            int id = (int)r;
            sidx[s] = id; s1[s] = sc1; s2[s] = sc2;
            sx[s] = cx; sy[s] = cy;
            cx += dict[((size_t)id * LSEG + (LSEG - 1)) * 2 + 0] * sc1;
            cy += dict[((size_t)id * LSEG + (LSEG - 1)) * 2 + 1] * sc2;
        }
    }
    __syncthreads();

    for (int i = threadIdx.x; i < SSEG * LSEG; i += blockDim.x) {
        int s = i / LSEG, l = i % LSEG;
        int id = sidx[s];
        float bx = dict[((size_t)id * LSEG + l) * 2 + 0];
        float by = dict[((size_t)id * LSEG + l) * 2 + 1];
        out[((size_t)b * SSEG * LSEG + i) * 2 + 0] = fmaf(bx, s1[s], sx[s]);
        out[((size_t)b * SSEG * LSEG + i) * 2 + 1] = fmaf(by, s2[s], sy[s]);
    }
}

// ---------------- launch ----------------
extern "C" void kernel_launch(void* const* d_in, const int* in_sizes, int n_in,
                              void* d_out, int out_size)
{
    const float* x   = (const float*)d_in[0];
    const float* w1  = (const float*)d_in[1];
    const float* b1  = (const float*)d_in[2];
    const float* w2  = (const float*)d_in[3];
    const float* b2  = (const float*)d_in[4];
    const float* w3  = (const float*)d_in[5];
    const float* b3  = (const float*)d_in[6];
    const float* w4  = (const float*)d_in[7];
    const float* b4  = (const float*)d_in[8];
    const float* fw1 = (const float*)d_in[9];
    const float* fb1 = (const float*)d_in[10];
    const float* fw2 = (const float*)d_in[11];
    const float* fb2 = (const float*)d_in[12];
    const float* fw3 = (const float*)d_in[13];
    const float* fb3 = (const float*)d_in[14];
    const float* dict= (const float*)d_in[15];
    float* out = (float*)d_out;

    float *h1, *h2, *h3, *h4, *a1, *a2, *pp, *w1k, *w2k, *w3k, *w4k, *part;
    cudaGetSymbolAddress((void**)&h1,  g_h1);
    cudaGetSymbolAddress((void**)&h2,  g_h2);
    cudaGetSymbolAddress((void**)&h3,  g_h3);
    cudaGetSymbolAddress((void**)&h4,  g_h4);
    cudaGetSymbolAddress((void**)&a1,  g_a1);
    cudaGetSymbolAddress((void**)&a2,  g_a2);
    cudaGetSymbolAddress((void**)&pp,  g_p);
    cudaGetSymbolAddress((void**)&w1k, g_w1k);
    cudaGetSymbolAddress((void**)&w2k, g_w2k);
    cudaGetSymbolAddress((void**)&w3k, g_w3k);
    cudaGetSymbolAddress((void**)&w4k, g_w4k);
    cudaGetSymbolAddress((void**)&part, g_part);

    // weight repack into channel-interleaved layout
    repack_wk<<<(64*3*9    + 255) / 256, 256>>>(w1, w1k, 3,   64);
    repack_wk<<<(128*64*9  + 255) / 256, 256>>>(w2, w2k, 64,  128);
    repack_wk<<<(256*128*9 + 255) / 256, 256>>>(w3, w3k, 128, 256);
    repack_wk<<<(512*256*9 + 255) / 256, 256>>>(w4, w4k, 256, 512);

    // stage 1: (128,3,100,100) -> (128,64,49,49)
    {
        int total = NB * (64/8) * 49 * 49;
        conv_pool_relu2<3,100,100,49,49,64><<<(total + 255) / 256, 256>>>(x, w1k, b1, h1);
    }
    // stage 2: -> (128,128,23,23)
    {
        int total = NB * (128/8) * 23 * 23;
        conv_pool_relu2<64,49,49,23,23,128><<<(total + 255) / 256, 256>>>(h1, w2k, b2, h2);
    }
    // stage 3: -> (128,256,10,10)
    {
        int total = NB * (256/8) * 10 * 10;
        conv_pool_relu2<128,23,23,10,10,256><<<(total + 255) / 256, 256>>>(h2, w3k, b3, h3);
    }
    // stage 4: -> (128,512,4,4) == flatten (128, 8192)
    {
        int total = NB * (512/8) * 4 * 4;
        conv_pool_relu2<256,10,10,4,4,512><<<(total + 255) / 256, 256>>>(h3, w4k, b4, h4);
    }

    // fc1: (128,8192) @ (8192,2048) + tanh, split-K=2 (128 blocks)
    {
        dim3 grid(2048 / 64, NB / 64, 2);
        gemm64_part<<<grid, 256>>>(h4, fw1, part, NB, 2048, 8192, 4096);
        combine_tanh<<<(NB * 2048 + 255) / 256, 256>>>(part, fb1, a1, NB, 2048);
    }
    // fc2: (128,2048) @ (2048,2048) + tanh
    {
        dim3 grid(2048 / 64, NB / 64);
        gemm64v2<1><<<grid, 256>>>(a1, fw2, fb2, a2, NB, 2048, 2048);
    }
    // fc3: (128,2048) @ (2048,62)
    fc_small<<<NB, 64>>>(a2, fw3, fb3, pp, OUTDIM, 2048);

    // trajectory assembly -> (128, 4000, 2)
    traj_kernel<<<NB, 256>>>(pp, dict, out);
}